// round 1
// baseline (speedup 1.0000x reference)
#include <cuda_runtime.h>
#include <math.h>

#define B 64
#define T 128
#define V 10000
#define E 1024
#define H 1024
#define G4 4096   // 4*H
#define L 2

// ---------------- scratch (device globals; no runtime allocation) ----------
__device__ float g_x[(size_t)B * T * E];     // layer input/output  (32 MB)
__device__ float g_gx[(size_t)B * T * G4];   // input projections   (128 MB)
__device__ float g_h[2][B * H];              // ping-pong hidden state
__device__ float g_c[B * H];                 // cell state
__device__ int   g_len[B];

// ---------------- lengths = row-sum of attention mask ----------------------
__global__ void lengths_kernel(const int* __restrict__ mask) {
    int b = blockIdx.x;
    int v = mask[b * T + threadIdx.x];
#pragma unroll
    for (int o = 16; o > 0; o >>= 1) v += __shfl_down_sync(0xffffffffu, v, o);
    __shared__ int sh[4];
    if ((threadIdx.x & 31) == 0) sh[threadIdx.x >> 5] = v;
    __syncthreads();
    if (threadIdx.x == 0) g_len[b] = sh[0] + sh[1] + sh[2] + sh[3];
}

// ---------------- embedding gather -----------------------------------------
__global__ void embed_kernel(const int* __restrict__ ids, const float* __restrict__ emb) {
    int r = blockIdx.x;                       // 0..B*T-1
    int id = __ldg(&ids[r]);
    const float4* s = reinterpret_cast<const float4*>(emb) + (size_t)id * (E / 4);
    float4* d = reinterpret_cast<float4*>(g_x) + (size_t)r * (E / 4);
    d[threadIdx.x] = s[threadIdx.x];          // 256 threads = E/4
}

// ---------------- zero h (both buffers) and c -------------------------------
__global__ void zero_hc() {
    int i = blockIdx.x * blockDim.x + threadIdx.x;
    if (i < B * H) { g_h[0][i] = 0.f; g_h[1][i] = 0.f; g_c[i] = 0.f; }
}

// ---------------- generic fp32 GEMM:  C = g_x * Wm^T + b1 (+ b2) ------------
// CTA tile 128x64, 256 threads, per-thread 8x4 micro-tile, reg-prefetch
// double buffering. mode 0: C = g_gx. mode 1: C = Cout.
__global__ void __launch_bounds__(256, 2) gemm_kernel(
    const float* __restrict__ Wm, const float* __restrict__ b1,
    const float* __restrict__ b2, float* __restrict__ Cout,
    int mode, int N, int K, int ldc)
{
    const float* __restrict__ A = g_x;
    float* __restrict__ C = (mode == 0) ? g_gx : Cout;

    __shared__ float As[16][132];   // [k][m], padded: 132*4B % 16 == 0
    __shared__ float Ws[16][68];    // [k][n]

    const int tid  = threadIdx.x;
    const int row0 = blockIdx.y * 128;
    const int col0 = blockIdx.x * 64;
    const int ty   = tid >> 4;      // 0..15 -> 8 rows each
    const int tx   = tid & 15;      // 0..15 -> 4 cols each

    float acc[8][4];
#pragma unroll
    for (int i = 0; i < 8; i++)
#pragma unroll
        for (int j = 0; j < 4; j++) acc[i][j] = 0.f;

    float4 ra[2], rw;
    // prefetch chunk 0
    {
#pragma unroll
        for (int i = 0; i < 2; i++) {
            int s = tid + i * 256; int r = s >> 2, kq = s & 3;
            ra[i] = *reinterpret_cast<const float4*>(&A[(size_t)(row0 + r) * K + kq * 4]);
        }
        int n = tid >> 2, kq = tid & 3; int col = col0 + n;
        rw = (col < N) ? *reinterpret_cast<const float4*>(&Wm[(size_t)col * K + kq * 4])
                       : make_float4(0.f, 0.f, 0.f, 0.f);
    }

    const int nCh = K >> 4;
    for (int ch = 0; ch < nCh; ch++) {
        // commit prefetched regs to smem
#pragma unroll
        for (int i = 0; i < 2; i++) {
            int s = tid + i * 256; int r = s >> 2, kq = s & 3;
            As[kq * 4 + 0][r] = ra[i].x; As[kq * 4 + 1][r] = ra[i].y;
            As[kq * 4 + 2][r] = ra[i].z; As[kq * 4 + 3][r] = ra[i].w;
        }
        { int n = tid >> 2, kq = tid & 3;
          Ws[kq * 4 + 0][n] = rw.x; Ws[kq * 4 + 1][n] = rw.y;
          Ws[kq * 4 + 2][n] = rw.z; Ws[kq * 4 + 3][n] = rw.w; }
        __syncthreads();

        if (ch + 1 < nCh) {
            int k0 = (ch + 1) << 4;
#pragma unroll
            for (int i = 0; i < 2; i++) {
                int s = tid + i * 256; int r = s >> 2, kq = s & 3;
                ra[i] = *reinterpret_cast<const float4*>(&A[(size_t)(row0 + r) * K + k0 + kq * 4]);
            }
            int n = tid >> 2, kq = tid & 3; int col = col0 + n;
            rw = (col < N) ? *reinterpret_cast<const float4*>(&Wm[(size_t)col * K + k0 + kq * 4])
                           : make_float4(0.f, 0.f, 0.f, 0.f);
        }

#pragma unroll
        for (int kk = 0; kk < 16; kk++) {
            float a[8], w[4];
            *reinterpret_cast<float4*>(&a[0]) = *reinterpret_cast<const float4*>(&As[kk][ty * 8]);
            *reinterpret_cast<float4*>(&a[4]) = *reinterpret_cast<const float4*>(&As[kk][ty * 8 + 4]);
            *reinterpret_cast<float4*>(&w[0]) = *reinterpret_cast<const float4*>(&Ws[kk][tx * 4]);
#pragma unroll
            for (int i = 0; i < 8; i++)
#pragma unroll
                for (int j = 0; j < 4; j++)
                    acc[i][j] = fmaf(a[i], w[j], acc[i][j]);
        }
        __syncthreads();
    }

    float bias[4];
#pragma unroll
    for (int j = 0; j < 4; j++) {
        int col = col0 + tx * 4 + j;
        bias[j] = (col < N) ? (b1[col] + (b2 ? b2[col] : 0.f)) : 0.f;
    }
#pragma unroll
    for (int i = 0; i < 8; i++) {
        int r = row0 + ty * 8 + i;
#pragma unroll
        for (int j = 0; j < 4; j++) {
            int col = col0 + tx * 4 + j;
            if (col < N) C[(size_t)r * ldc + col] = acc[i][j] + bias[j];
        }
    }
}

// ---------------- fused LSTM step: gates GEMM + cell update -----------------
// grid = H/8 = 128 CTAs. CTA owns h-columns [j0, j0+8) -> a 64x32 gate tile
// (cols {g*H + j0+jj : g in 0..3}). K = H = 1024 reduction over h_in.
__global__ void __launch_bounds__(128) lstm_step_kernel(
    const float* __restrict__ Whh, int t)
{
    __shared__ float hsm[32][68];   // [k][b]
    __shared__ float wsm[32][36];   // [k][q]
    __shared__ float Ssm[64][33];   // gate pre-activations

    const float* __restrict__ hin  = g_h[t & 1];
    float* __restrict__       hout = g_h[(t + 1) & 1];

    const int tid = threadIdx.x;
    const int j0  = blockIdx.x * 8;
    const int ty  = tid >> 3;       // 0..15 -> 4 rows (batch) each
    const int tx  = tid & 7;        // 0..7  -> 4 gate-cols each

    float acc[4][4];
#pragma unroll
    for (int i = 0; i < 4; i++)
#pragma unroll
        for (int j = 0; j < 4; j++) acc[i][j] = 0.f;

    float4 rh[4], rw[2];
    // prefetch chunk 0 (KC = 32)
#pragma unroll
    for (int i = 0; i < 4; i++) {
        int s = tid + i * 128; int b = s >> 3, kq = s & 7;
        rh[i] = *reinterpret_cast<const float4*>(&hin[b * H + kq * 4]);
    }
#pragma unroll
    for (int i = 0; i < 2; i++) {
        int s = tid + i * 128; int q = s >> 3, kq = s & 7;
        int wr = (q >> 3) * H + j0 + (q & 7);
        rw[i] = *reinterpret_cast<const float4*>(&Whh[(size_t)wr * H + kq * 4]);
    }

    for (int ch = 0; ch < 32; ch++) {
#pragma unroll
        for (int i = 0; i < 4; i++) {
            int s = tid + i * 128; int b = s >> 3, kq = s & 7;
            hsm[kq * 4 + 0][b] = rh[i].x; hsm[kq * 4 + 1][b] = rh[i].y;
            hsm[kq * 4 + 2][b] = rh[i].z; hsm[kq * 4 + 3][b] = rh[i].w;
        }
#pragma unroll
        for (int i = 0; i < 2; i++) {
            int s = tid + i * 128; int q = s >> 3, kq = s & 7;
            wsm[kq * 4 + 0][q] = rw[i].x; wsm[kq * 4 + 1][q] = rw[i].y;
            wsm[kq * 4 + 2][q] = rw[i].z; wsm[kq * 4 + 3][q] = rw[i].w;
        }
        __syncthreads();

        if (ch + 1 < 32) {
            int k0 = (ch + 1) * 32;
#pragma unroll
            for (int i = 0; i < 4; i++) {
                int s = tid + i * 128; int b = s >> 3, kq = s & 7;
                rh[i] = *reinterpret_cast<const float4*>(&hin[b * H + k0 + kq * 4]);
            }
#pragma unroll
            for (int i = 0; i < 2; i++) {
                int s = tid + i * 128; int q = s >> 3, kq = s & 7;
                int wr = (q >> 3) * H + j0 + (q & 7);
                rw[i] = *reinterpret_cast<const float4*>(&Whh[(size_t)wr * H + k0 + kq * 4]);
            }
        }

#pragma unroll
        for (int kk = 0; kk < 32; kk++) {
            float a[4], w[4];
            *reinterpret_cast<float4*>(&a[0]) = *reinterpret_cast<const float4*>(&hsm[kk][ty * 4]);
            *reinterpret_cast<float4*>(&w[0]) = *reinterpret_cast<const float4*>(&wsm[kk][tx * 4]);
#pragma unroll
            for (int i = 0; i < 4; i++)
#pragma unroll
                for (int j = 0; j < 4; j++)
                    acc[i][j] = fmaf(a[i], w[j], acc[i][j]);
        }
        __syncthreads();
    }

    // exchange gate tile through smem so each thread sees all 4 gates of (b, j)
#pragma unroll
    for (int i = 0; i < 4; i++)
#pragma unroll
        for (int j = 0; j < 4; j++) Ssm[ty * 4 + i][tx * 4 + j] = acc[i][j];
    __syncthreads();

#pragma unroll
    for (int ii = 0; ii < 4; ii++) {
        int idx = tid * 4 + ii;               // 0..511 = 64 batches x 8 cols
        int b = idx >> 3, jj = idx & 7;
        int j = j0 + jj;
        size_t gr = ((size_t)b * T + t) * G4;
        float iv = Ssm[b][jj]      + g_gx[gr + j];
        float fv = Ssm[b][8 + jj]  + g_gx[gr + H + j];
        float gv = Ssm[b][16 + jj] + g_gx[gr + 2 * H + j];
        float ov = Ssm[b][24 + jj] + g_gx[gr + 3 * H + j];

        float c_old = g_c[b * H + j];
        float h_old = hin[b * H + j];

        float si = 1.f / (1.f + expf(-iv));
        float sf = 1.f / (1.f + expf(-fv));
        float so = 1.f / (1.f + expf(-ov));
        float cn = fmaf(sf, c_old, si * tanhf(gv));
        float hn = so * tanhf(cn);

        bool ok = t < g_len[b];
        g_c[b * H + j]  = ok ? cn : c_old;
        hout[b * H + j] = ok ? hn : h_old;
        g_x[((size_t)b * T + t) * E + j] = ok ? hn : 0.f;   // zero-padded output
    }
}

// ---------------- final state copy ------------------------------------------
__global__ void copy_states_kernel(float* __restrict__ hs_out, float* __restrict__ cs_out) {
    int i = blockIdx.x * blockDim.x + threadIdx.x;
    if (i < B * H) {
        hs_out[i] = g_h[0][i];   // after T=128 steps, final h lives in buffer 0
        cs_out[i] = g_c[i];
    }
}

// ---------------- launch ------------------------------------------------------
extern "C" void kernel_launch(void* const* d_in, const int* in_sizes, int n_in,
                              void* d_out, int out_size)
{
    const int*   ids  = (const int*)d_in[0];
    const int*   mask = (const int*)d_in[1];
    const float* emb  = (const float*)d_in[2];
    const float* Wih  = (const float*)d_in[3];
    const float* Whh  = (const float*)d_in[4];
    const float* bih  = (const float*)d_in[5];
    const float* bhh  = (const float*)d_in[6];
    const float* fcw  = (const float*)d_in[7];
    const float* fcb  = (const float*)d_in[8];
    float* out = (float*)d_out;

    lengths_kernel<<<B, T>>>(mask);
    embed_kernel<<<B * T, E / 4>>>(ids, emb);

    const size_t HS_OFF = (size_t)B * T * V;           // 81,920,000
    const size_t CS_OFF = HS_OFF + (size_t)L * B * H;  // + 131,072

    for (int l = 0; l < L; l++) {
        // gx = x @ W_ih[l]^T + (b_ih[l] + b_hh[l])   : [8192, 4096]
        gemm_kernel<<<dim3(G4 / 64, (B * T) / 128), 256>>>(
            Wih + (size_t)l * G4 * E, bih + (size_t)l * G4, bhh + (size_t)l * G4,
            nullptr, /*mode=*/0, G4, E, G4);

        zero_hc<<<(B * H + 511) / 512, 512>>>();

        for (int t = 0; t < T; t++)
            lstm_step_kernel<<<H / 8, 128>>>(Whh + (size_t)l * G4 * H, t);

        copy_states_kernel<<<(B * H + 511) / 512, 512>>>(
            out + HS_OFF + (size_t)l * B * H,
            out + CS_OFF + (size_t)l * B * H);
    }

    // logits = x @ fc_w^T + fc_b : [8192, 10000] written straight into d_out
    gemm_kernel<<<dim3((V + 63) / 64, (B * T) / 128), 256>>>(
        fcw, fcb, nullptr, out, /*mode=*/1, V, H, V);
}